// round 11
// baseline (speedup 1.0000x reference)
#include <cuda_runtime.h>
#include <cuda_bf16.h>

// DNM_Linear: out[b,o] = relu(0.25 * sum_{m,i} relu(x[b,i]*W[o,m,i] - q[o,m,i]) - 0.05)
// x: [512,512] f32; W,q: [128,8,512] -> flat [1024,512] f32; out: [512,128] f32
//
// Split-K (2 CTAs per output tile): main kernel accumulates each K-half into
// __device__ scratch raw[2][512][128]; combine kernel applies the activation.
// Main: 512 thr/CTA (4 warps/SMSP), tile 128(batch)x64(neuron), thread tile
// 8 rows x 4 cols, warp = 16 tx x 2 ty with ty splitting K parity, f32x2 math.

#define IN_DIM   512
#define OUT_DIM  128
#define B_TOT    512
#define KHALF    256
#define KC       32
#define NCHUNK   8             // KHALF / KC
#define NMAC     8             // macro steps per chunk (2 kk each)
#define XP       260           // x row pitch: 128 rows x 2 + 4 pad
#define WP       132           // w/q row pitch: 64 rows x 2 + 4 pad
#define XARR     (16*XP)       // 4160 floats
#define WARR     (16*WP)       // 2112 floats
#define BUFF     (XARR + 2*WARR)   // 8384 floats per buffer
#define SMEM_BYTES (2*BUFF*4)      // 67072 B

typedef unsigned long long u64;

__device__ float g_raw[2 * B_TOT * OUT_DIM];   // [kz][b][o] partial sums

__device__ __forceinline__ u64 fma2(u64 a, u64 b, u64 c) {
    u64 d; asm("fma.rn.f32x2 %0, %1, %2, %3;" : "=l"(d) : "l"(a), "l"(b), "l"(c)); return d;
}
__device__ __forceinline__ u64 add2(u64 a, u64 b) {
    u64 d; asm("add.rn.f32x2 %0, %1, %2;" : "=l"(d) : "l"(a), "l"(b)); return d;
}
__device__ __forceinline__ u64 relu2(u64 v) {
    float2 f = *reinterpret_cast<float2*>(&v);
    f.x = fmaxf(f.x, 0.f);
    f.y = fmaxf(f.y, 0.f);
    return *reinterpret_cast<u64*>(&f);
}

extern __shared__ float smem[];

__device__ __forceinline__ void stage_store(float* sb, int soff, int pitch,
                                            int lrow, int lkh, float sgn,
                                            const float4 v[4])
{
#pragma unroll
    for (int j = 0; j < 4; j++) {
        const int kk = lkh * 8 + j * 2;
        *(float2*)(sb + soff + (kk    ) * pitch + lrow * 2) = make_float2(sgn * v[j].x, sgn * v[j].y);
        *(float2*)(sb + soff + (kk + 1) * pitch + lrow * 2) = make_float2(sgn * v[j].z, sgn * v[j].w);
    }
}

__global__ __launch_bounds__(512, 1)
void dnm_main(const float* __restrict__ x,
              const float* __restrict__ W,
              const float* __restrict__ q)
{
    const int t    = threadIdx.x;
    const int lane = t & 31;
    const int wid  = t >> 5;          // 0..15 -> rows wid*8 .. wid*8+7
    const int tx   = lane & 15;
    const int ty   = lane >> 4;       // kk parity within macro step
    const int n0   = blockIdx.x * 64;     // neuron tile (64 neurons)
    const int b0   = blockIdx.y * 128;    // batch tile (128 rows)
    const int kz   = blockIdx.z;          // K half
    const int kbase = kz * KHALF;

    // ---- loader role: t<256 -> x (128 rows), t<384 -> W (64), else -> q (64, negated)
    int lrow, lkh, soff, pitch;
    float sgn;
    const float* gsrc;
    if (t < 256) {
        lrow = t & 127; lkh = (t >> 7) & 1;
        gsrc = x + (size_t)(b0 + lrow) * IN_DIM + kbase + lkh * 16;
        soff = 0; pitch = XP; sgn = 1.f;
    } else if (t < 384) {
        const int idx = t - 256;
        lrow = idx & 63; lkh = idx >> 6;
        gsrc = W + (size_t)(n0 + lrow) * IN_DIM + kbase + lkh * 16;
        soff = XARR; pitch = WP; sgn = 1.f;
    } else {
        const int idx = t - 384;
        lrow = idx & 63; lkh = idx >> 6;
        gsrc = q + (size_t)(n0 + lrow) * IN_DIM + kbase + lkh * 16;
        soff = XARR + WARR; pitch = WP; sgn = -1.f;
    }

    u64 acc[8][4];
#pragma unroll
    for (int r = 0; r < 8; r++)
#pragma unroll
        for (int j = 0; j < 4; j++) acc[r][j] = 0ull;

    float4 pf[4];

    // ---- prologue: load + store chunk 0
#pragma unroll
    for (int j = 0; j < 4; j++) pf[j] = *(const float4*)(gsrc + j * 4);
    stage_store(smem, soff, pitch, lrow, lkh, sgn, pf);
    __syncthreads();

    for (int c = 0; c < NCHUNK; c++) {
        // global prefetch for chunk c+1 (stored mid-loop below)
        if (c < NCHUNK - 1) {
            const int kn = (c + 1) * KC;
#pragma unroll
            for (int j = 0; j < 4; j++) pf[j] = *(const float4*)(gsrc + kn + j * 4);
        }

        const float* cb = smem + (c & 1) * BUFF;
        const float* bx = cb + ty * XP + wid * 16;
        const float* bw = cb + XARR + ty * WP + tx * 4;
        const float* bq = cb + XARR + WARR + ty * WP + tx * 4;

#pragma unroll
        for (int m = 0; m < NMAC; m++) {
            const int xo = m * (2 * XP);
            const int wo = m * (2 * WP);

            float4 xv0 = *(const float4*)(bx + xo);        // rows 0-1 (k-pairs)
            float4 xv1 = *(const float4*)(bx + xo + 4);    // rows 2-3
            float4 xv2 = *(const float4*)(bx + xo + 8);    // rows 4-5
            float4 xv3 = *(const float4*)(bx + xo + 12);   // rows 6-7
            float4 wv0 = *(const float4*)(bw + wo);        // cols 2tx,2tx+1
            float4 wv1 = *(const float4*)(bw + wo + 64);   // cols 32+2tx,33+2tx
            float4 qv0 = *(const float4*)(bq + wo);
            float4 qv1 = *(const float4*)(bq + wo + 64);

            // mid-loop: stage prefetched globals into the other smem buffer
            if (m == 4 && c < NCHUNK - 1) {
                stage_store(smem + ((c + 1) & 1) * BUFF, soff, pitch, lrow, lkh, sgn, pf);
            }

            u64 ux[8] = { *(u64*)&xv0.x, *(u64*)&xv0.z,
                          *(u64*)&xv1.x, *(u64*)&xv1.z,
                          *(u64*)&xv2.x, *(u64*)&xv2.z,
                          *(u64*)&xv3.x, *(u64*)&xv3.z };
            u64 uw[4] = { *(u64*)&wv0.x, *(u64*)&wv0.z,
                          *(u64*)&wv1.x, *(u64*)&wv1.z };
            u64 uq[4] = { *(u64*)&qv0.x, *(u64*)&qv0.z,
                          *(u64*)&qv1.x, *(u64*)&qv1.z };

#pragma unroll
            for (int r = 0; r < 8; r++)
#pragma unroll
                for (int j = 0; j < 4; j++)
                    acc[r][j] = add2(acc[r][j], relu2(fma2(ux[r], uw[j], uq[j])));
        }

        __syncthreads();
    }

    // ---- fold k-parity (xor16), then 8-neuron groups (xor1, xor2); write raw sums
    const unsigned FULL = 0xffffffffu;
    float* raw = g_raw + kz * (B_TOT * OUT_DIM);
#pragma unroll
    for (int r = 0; r < 8; r++) {
        float2 a0 = *reinterpret_cast<float2*>(&acc[r][0]);
        float2 a1 = *reinterpret_cast<float2*>(&acc[r][1]);
        float2 a2 = *reinterpret_cast<float2*>(&acc[r][2]);
        float2 a3 = *reinterpret_cast<float2*>(&acc[r][3]);
        float sA = a0.x + a0.y + a1.x + a1.y;   // cols 2tx, 2tx+1
        float sB = a2.x + a2.y + a3.x + a3.y;   // cols 32+2tx, 33+2tx

        sA += __shfl_xor_sync(FULL, sA, 16);
        sB += __shfl_xor_sync(FULL, sB, 16);
        sA += __shfl_xor_sync(FULL, sA, 1);
        sB += __shfl_xor_sync(FULL, sB, 1);
        sA += __shfl_xor_sync(FULL, sA, 2);
        sB += __shfl_xor_sync(FULL, sB, 2);

        if ((lane & 19) == 0) {                 // ty==0 && (tx&3)==0
            const int b  = b0 + wid * 8 + r;
            const int g  = tx >> 2;             // 0..3
            const int ob = n0 >> 3;
            raw[b * OUT_DIM + ob + g]     = sA;
            raw[b * OUT_DIM + ob + 4 + g] = sB;
        }
    }
}

__global__ __launch_bounds__(256, 1)
void dnm_combine(float* __restrict__ out)
{
    const int i = (blockIdx.x * 256 + threadIdx.x) * 4;   // 64 CTAs x 256 thr x 4
    float4 a = *(const float4*)(g_raw + i);
    float4 b = *(const float4*)(g_raw + B_TOT * OUT_DIM + i);
    float4 o;
    o.x = fmaxf(0.25f * (a.x + b.x) - 0.05f, 0.f);
    o.y = fmaxf(0.25f * (a.y + b.y) - 0.05f, 0.f);
    o.z = fmaxf(0.25f * (a.z + b.z) - 0.05f, 0.f);
    o.w = fmaxf(0.25f * (a.w + b.w) - 0.05f, 0.f);
    *(float4*)(out + i) = o;
}

extern "C" void kernel_launch(void* const* d_in, const int* in_sizes, int n_in,
                              void* d_out, int out_size)
{
    const float* x = (const float*)d_in[0];
    const float* W = (const float*)d_in[1];
    const float* q = (const float*)d_in[2];
    float* out = (float*)d_out;

    cudaFuncSetAttribute(dnm_main, cudaFuncAttributeMaxDynamicSharedMemorySize, SMEM_BYTES);

    dim3 grid(1024 / 64, B_TOT / 128, 2);   // 16 x 4 x 2 = 128 CTAs
    dnm_main<<<grid, 512, SMEM_BYTES>>>(x, W, q);
    dnm_combine<<<(B_TOT * OUT_DIM) / (256 * 4), 256>>>(out);
}

// round 13
// speedup vs baseline: 1.2786x; 1.2786x over previous
#include <cuda_runtime.h>
#include <cuda_bf16.h>

// DNM_Linear: out[b,o] = relu(0.25 * sum_{m,i} relu(x[b,i]*W[o,m,i] - q[o,m,i]) - 0.05)
// x: [512,512] f32; W,q: [128,8,512] -> flat [1024,512] f32; out: [512,128] f32
//
// 512 thr/CTA, tile 64(b)x64(n). Warp = 16 tx (2 batch rows each) x 2 ty (k parity).
// wid = (cg, rg): cg -> 8 neuron cols (one full m-group = one output), rg -> 32-row half.
// w/q smem loads are warp-broadcast (1 wf); only x pays fan-out. f32x2 along K.

#define IN_DIM   512
#define OUT_DIM  128
#define NEUR     1024
#define B_TOT    512
#define KC       32
#define NMAC     8             // macro steps per chunk (2 kk each)
#define ROWF     132           // 64 entity-pairs + 4 pad floats
#define ARR      (16*ROWF)     // kk-rows per chunk * pitch
#define BUF      (3*ARR)
#define SMEM_BYTES (2*BUF*4)   // 50688 B

typedef unsigned long long u64;

__device__ __forceinline__ u64 fma2(u64 a, u64 b, u64 c) {
    u64 d; asm("fma.rn.f32x2 %0, %1, %2, %3;" : "=l"(d) : "l"(a), "l"(b), "l"(c)); return d;
}
__device__ __forceinline__ u64 add2(u64 a, u64 b) {
    u64 d; asm("add.rn.f32x2 %0, %1, %2;" : "=l"(d) : "l"(a), "l"(b)); return d;
}
__device__ __forceinline__ u64 relu2(u64 v) {
    float2 f = *reinterpret_cast<float2*>(&v);
    f.x = fmaxf(f.x, 0.f);
    f.y = fmaxf(f.y, 0.f);
    return *reinterpret_cast<u64*>(&f);
}

extern __shared__ float smem[];

__global__ __launch_bounds__(512, 1)
void dnm_kernel(const float* __restrict__ x,
                const float* __restrict__ W,
                const float* __restrict__ q,
                float* __restrict__ out)
{
    const int t    = threadIdx.x;
    const int lane = t & 31;
    const int wid  = t >> 5;
    const int tx   = lane & 15;
    const int ty   = lane >> 4;       // kk parity within macro step
    const int cg   = wid & 7;         // neuron cols cg*8 .. cg*8+7 (one m-group)
    const int rg   = wid >> 3;        // batch rows rg*32 + tx*2 + {0,1}
    const int n0   = blockIdx.x * 64;
    const int b0   = blockIdx.y * 64;

    // global load mapping: 8 threads per entity row, 1 float4 each
    const int e  = t >> 3;
    const int kq = (t & 7) * 4;
    const float* xg = x + (size_t)(b0 + e) * IN_DIM + kq;
    const float* wg = W + (size_t)(n0 + e) * IN_DIM + kq;
    const float* qg = q + (size_t)(n0 + e) * IN_DIM + kq;
    const int kk0 = kq >> 1;

    // acc[r][g]: batch row rg*32+tx*2+r, neuron col cg*8+g (k-pair partials)
    u64 acc[2][8];
#pragma unroll
    for (int r = 0; r < 2; r++)
#pragma unroll
        for (int g = 0; g < 8; g++) acc[r][g] = 0ull;

    float4 px, pw, pq;

    // ---- prologue: load + store chunk 0
    px = *(const float4*)xg;
    pw = *(const float4*)wg;
    pq = *(const float4*)qg;
    {
        float* bx = smem;
        float* bw = smem + ARR;
        float* bq = smem + 2 * ARR;
        *(float2*)(bx + (kk0    ) * ROWF + e * 2) = make_float2(px.x,  px.y);
        *(float2*)(bx + (kk0 + 1) * ROWF + e * 2) = make_float2(px.z,  px.w);
        *(float2*)(bw + (kk0    ) * ROWF + e * 2) = make_float2(pw.x,  pw.y);
        *(float2*)(bw + (kk0 + 1) * ROWF + e * 2) = make_float2(pw.z,  pw.w);
        *(float2*)(bq + (kk0    ) * ROWF + e * 2) = make_float2(-pq.x, -pq.y);
        *(float2*)(bq + (kk0 + 1) * ROWF + e * 2) = make_float2(-pq.z, -pq.w);
    }
    __syncthreads();

    const int NCHUNK = IN_DIM / KC;   // 16

    for (int c = 0; c < NCHUNK; c++) {
        // global prefetch for chunk c+1 (stored mid-loop below)
        if (c < NCHUNK - 1) {
            const int kn = (c + 1) * KC;
            px = *(const float4*)(xg + kn);
            pw = *(const float4*)(wg + kn);
            pq = *(const float4*)(qg + kn);
        }

        const float* cb = smem + (c & 1) * BUF;
        const float* bx = cb + ty * ROWF + rg * 64 + tx * 4;   // 2 rows (1 float4)
        const float* bw = cb + ARR + ty * ROWF + cg * 16;      // 8 cols (4 float4), broadcast
        const float* bq = cb + 2 * ARR + ty * ROWF + cg * 16;

#pragma unroll
        for (int m = 0; m < NMAC; m++) {
            const int off = m * (2 * ROWF);

            float4 xv  = *(const float4*)(bx + off);           // rows tx*2, tx*2+1
            float4 wv0 = *(const float4*)(bw + off);           // cols 0-1
            float4 wv1 = *(const float4*)(bw + off + 4);       // cols 2-3
            float4 wv2 = *(const float4*)(bw + off + 8);       // cols 4-5
            float4 wv3 = *(const float4*)(bw + off + 12);      // cols 6-7
            float4 qv0 = *(const float4*)(bq + off);
            float4 qv1 = *(const float4*)(bq + off + 4);
            float4 qv2 = *(const float4*)(bq + off + 8);
            float4 qv3 = *(const float4*)(bq + off + 12);

            // mid-loop: store prefetched globals into the other smem buffer
            if (m == 4 && c < NCHUNK - 1) {
                float* nb = smem + ((c + 1) & 1) * BUF;
                float* bx2 = nb;
                float* bw2 = nb + ARR;
                float* bq2 = nb + 2 * ARR;
                *(float2*)(bx2 + (kk0    ) * ROWF + e * 2) = make_float2(px.x,  px.y);
                *(float2*)(bx2 + (kk0 + 1) * ROWF + e * 2) = make_float2(px.z,  px.w);
                *(float2*)(bw2 + (kk0    ) * ROWF + e * 2) = make_float2(pw.x,  pw.y);
                *(float2*)(bw2 + (kk0 + 1) * ROWF + e * 2) = make_float2(pw.z,  pw.w);
                *(float2*)(bq2 + (kk0    ) * ROWF + e * 2) = make_float2(-pq.x, -pq.y);
                *(float2*)(bq2 + (kk0 + 1) * ROWF + e * 2) = make_float2(-pq.z, -pq.w);
            }

            u64 ux[2] = { *(u64*)&xv.x, *(u64*)&xv.z };
            u64 uw[8] = { *(u64*)&wv0.x, *(u64*)&wv0.z, *(u64*)&wv1.x, *(u64*)&wv1.z,
                          *(u64*)&wv2.x, *(u64*)&wv2.z, *(u64*)&wv3.x, *(u64*)&wv3.z };
            u64 uq[8] = { *(u64*)&qv0.x, *(u64*)&qv0.z, *(u64*)&qv1.x, *(u64*)&qv1.z,
                          *(u64*)&qv2.x, *(u64*)&qv2.z, *(u64*)&qv3.x, *(u64*)&qv3.z };

#pragma unroll
            for (int r = 0; r < 2; r++)
#pragma unroll
                for (int g = 0; g < 8; g++)
                    acc[r][g] = add2(acc[r][g], relu2(fma2(ux[r], uw[g], uq[g])));
        }

        __syncthreads();
    }

    // ---- epilogue: in-thread add2 tree over the 8 cols (one m-group), fold k-parity
    const unsigned FULL = 0xffffffffu;
#pragma unroll
    for (int r = 0; r < 2; r++) {
        u64 t0 = add2(add2(acc[r][0], acc[r][1]), add2(acc[r][2], acc[r][3]));
        u64 t1 = add2(add2(acc[r][4], acc[r][5]), add2(acc[r][6], acc[r][7]));
        u64 tt = add2(t0, t1);
        float2 f = *reinterpret_cast<float2*>(&tt);
        float s = f.x + f.y;

        s += __shfl_xor_sync(FULL, s, 16);      // fold k parity (ty)

        if (ty == 0) {
            const int b = b0 + rg * 32 + tx * 2 + r;
            const int o = (n0 >> 3) + cg;
            out[b * OUT_DIM + o] = fmaxf(0.25f * s - 0.05f, 0.f);
        }
    }
}

extern "C" void kernel_launch(void* const* d_in, const int* in_sizes, int n_in,
                              void* d_out, int out_size)
{
    const float* x = (const float*)d_in[0];
    const float* W = (const float*)d_in[1];
    const float* q = (const float*)d_in[2];
    float* out = (float*)d_out;

    cudaFuncSetAttribute(dnm_kernel, cudaFuncAttributeMaxDynamicSharedMemorySize, SMEM_BYTES);

    dim3 grid(NEUR / 64, B_TOT / 64);   // 128 CTAs, 512 threads
    dnm_kernel<<<grid, 512, SMEM_BYTES>>>(x, W, q, out);
}

// round 14
// speedup vs baseline: 1.5312x; 1.1975x over previous
#include <cuda_runtime.h>
#include <cuda_fp16.h>

// DNM_Linear: out[b,o] = relu(0.25 * sum_{m,i} relu(x[b,i]*W[o,m,i] - q[o,m,i]) - 0.05)
// x: [512,512] f32; W,q: [128,8,512] -> flat [1024,512] f32; out: [512,128] f32
//
// fp16 mainloop: HFMA2/HMAX2/HADD2 (rt 2 vs effective rt 4 for f32x2) with f32
// chunk flush. 512 thr/CTA, tile 64x64, warp = 16 tx (2 rows) x 2 ty (k parity),
// wid=(cg,rg): cg -> one m-group of 8 neuron cols (broadcast w/q), rg -> row half.

#define IN_DIM   512
#define OUT_DIM  128
#define NEUR     1024
#define B_TOT    512
#define KC       32
#define NMAC     8               // macro steps per chunk (2 kk each)
#define PITCH2   68              // half2 per kk-row (64 entities + 4 pad)
#define ARR2     (16*PITCH2)     // 1088 half2 per array
#define BUF2     (3*ARR2)        // x, w, -q
#define SMEM_BYTES (2*BUF2*4)    // 26112 B

typedef unsigned long long u64;

extern __shared__ __half2 smh[];

__device__ __forceinline__ void stage(__half2* base, int kk0, int e,
                                      const float4& px, const float4& pw, const float4& pq)
{
    base[(kk0    ) * PITCH2 + e]            = __floats2half2_rn(px.x, px.y);
    base[(kk0 + 1) * PITCH2 + e]            = __floats2half2_rn(px.z, px.w);
    base[ARR2 + (kk0    ) * PITCH2 + e]     = __floats2half2_rn(pw.x, pw.y);
    base[ARR2 + (kk0 + 1) * PITCH2 + e]     = __floats2half2_rn(pw.z, pw.w);
    base[2*ARR2 + (kk0    ) * PITCH2 + e]   = __floats2half2_rn(-pq.x, -pq.y);
    base[2*ARR2 + (kk0 + 1) * PITCH2 + e]   = __floats2half2_rn(-pq.z, -pq.w);
}

__global__ __launch_bounds__(512, 1)
void dnm_kernel(const float* __restrict__ x,
                const float* __restrict__ W,
                const float* __restrict__ q,
                float* __restrict__ out)
{
    const int t    = threadIdx.x;
    const int lane = t & 31;
    const int wid  = t >> 5;
    const int tx   = lane & 15;
    const int ty   = lane >> 4;       // kk parity within macro step
    const int cg   = wid & 7;         // neuron cols cg*8 .. cg*8+7 (one m-group)
    const int rg   = wid >> 3;        // batch rows rg*32 + tx*2 + {0,1}
    const int n0   = blockIdx.x * 64;
    const int b0   = blockIdx.y * 64;

    // global load mapping: 8 threads per entity row, 1 float4 each
    const int e  = t >> 3;
    const int kq = (t & 7) * 4;
    const float* xg = x + (size_t)(b0 + e) * IN_DIM + kq;
    const float* wg = W + (size_t)(n0 + e) * IN_DIM + kq;
    const float* qg = q + (size_t)(n0 + e) * IN_DIM + kq;
    const int kk0 = kq >> 1;

    // f32 totals: rows {0,1} x 8 cols (lane pair of half2 folded at flush)
    float2 facc[2][8];
#pragma unroll
    for (int r = 0; r < 2; r++)
#pragma unroll
        for (int g = 0; g < 8; g++) facc[r][g] = make_float2(0.f, 0.f);

    const __half2 hzero = __float2half2_rn(0.f);

    float4 px, pw, pq;

    // ---- prologue: load + stage chunk 0
    px = *(const float4*)xg;
    pw = *(const float4*)wg;
    pq = *(const float4*)qg;
    stage(smh, kk0, e, px, pw, pq);
    __syncthreads();

    const int NCHUNK = IN_DIM / KC;   // 16

    for (int c = 0; c < NCHUNK; c++) {
        // global prefetch for chunk c+1 (staged mid-loop below)
        if (c < NCHUNK - 1) {
            const int kn = (c + 1) * KC;
            px = *(const float4*)(xg + kn);
            pw = *(const float4*)(wg + kn);
            pq = *(const float4*)(qg + kn);
        }

        const __half2* cb  = smh + (c & 1) * BUF2;
        const __half2* bxp = cb + rg * 32 + tx * 2;
        const __half2* bwp = cb + ARR2 + cg * 8;
        const __half2* bqp = cb + 2 * ARR2 + cg * 8;

        // fp16 chunk accumulators (<= 16 elems per lane per chain)
        __half2 hacc[2][8];
#pragma unroll
        for (int r = 0; r < 2; r++)
#pragma unroll
            for (int g = 0; g < 8; g++) hacc[r][g] = hzero;

#pragma unroll
        for (int m = 0; m < NMAC; m++) {
            const int off = (2 * m + ty) * PITCH2;

            u64 xv = *reinterpret_cast<const u64*>(bxp + off);      // rows tx*2, tx*2+1
            uint4 wa = *reinterpret_cast<const uint4*>(bwp + off);      // cols 0-3
            uint4 wb = *reinterpret_cast<const uint4*>(bwp + off + 4);  // cols 4-7
            uint4 qa = *reinterpret_cast<const uint4*>(bqp + off);
            uint4 qb = *reinterpret_cast<const uint4*>(bqp + off + 4);

            // mid-loop: stage prefetched globals into the other smem buffer
            if (m == 4 && c < NCHUNK - 1) {
                stage(smh + ((c + 1) & 1) * BUF2, kk0, e, px, pw, pq);
            }

            const __half2* hx = reinterpret_cast<const __half2*>(&xv);
            const __half2* hw0 = reinterpret_cast<const __half2*>(&wa);
            const __half2* hw1 = reinterpret_cast<const __half2*>(&wb);
            const __half2* hq0 = reinterpret_cast<const __half2*>(&qa);
            const __half2* hq1 = reinterpret_cast<const __half2*>(&qb);

#pragma unroll
            for (int r = 0; r < 2; r++) {
#pragma unroll
                for (int g = 0; g < 4; g++) {
                    hacc[r][g]     = __hadd2(hacc[r][g],
                                      __hmax2(__hfma2(hx[r], hw0[g], hq0[g]), hzero));
                    hacc[r][g + 4] = __hadd2(hacc[r][g + 4],
                                      __hmax2(__hfma2(hx[r], hw1[g], hq1[g]), hzero));
                }
            }
        }

        // ---- flush fp16 chunk partials into f32 totals
#pragma unroll
        for (int r = 0; r < 2; r++)
#pragma unroll
            for (int g = 0; g < 8; g++) {
                float2 f = __half22float2(hacc[r][g]);
                facc[r][g].x += f.x;
                facc[r][g].y += f.y;
            }

        __syncthreads();
    }

    // ---- epilogue: in-thread sum over 8 cols (one m-group), fold k-parity (xor16)
    const unsigned FULL = 0xffffffffu;
#pragma unroll
    for (int r = 0; r < 2; r++) {
        float s = 0.f;
#pragma unroll
        for (int g = 0; g < 8; g++)
            s += facc[r][g].x + facc[r][g].y;

        s += __shfl_xor_sync(FULL, s, 16);      // fold k parity (ty)

        if (ty == 0) {
            const int b = b0 + rg * 32 + tx * 2 + r;
            const int o = (n0 >> 3) + cg;
            out[b * OUT_DIM + o] = fmaxf(0.25f * s - 0.05f, 0.f);
        }
    }
}

extern "C" void kernel_launch(void* const* d_in, const int* in_sizes, int n_in,
                              void* d_out, int out_size)
{
    const float* x = (const float*)d_in[0];
    const float* W = (const float*)d_in[1];
    const float* q = (const float*)d_in[2];
    float* out = (float*)d_out;

    cudaFuncSetAttribute(dnm_kernel, cudaFuncAttributeMaxDynamicSharedMemorySize, SMEM_BYTES);

    dim3 grid(NEUR / 64, B_TOT / 64);   // 128 CTAs, 512 threads
    dnm_kernel<<<grid, 512, SMEM_BYTES>>>(x, W, q, out);
}

// round 15
// speedup vs baseline: 1.6243x; 1.0608x over previous
#include <cuda_runtime.h>
#include <cuda_fp16.h>

// DNM_Linear: out[b,o] = relu(0.25 * sum_{m,i} relu(x[b,i]*W[o,m,i] - q[o,m,i]) - 0.05)
// x: [512,512] f32; W,q: [128,8,512] -> flat [1024,512] f32; out: [512,128] f32
//
// fp16 mainloop (HFMA2/HMAX2/HADD2) with f32 flush per KC=64 chunk.
// 512 thr/CTA, tile 64x64, warp = 16 tx (2 rows) x 2 ty (k parity),
// wid=(cg,rg): cg -> one m-group of 8 neuron cols (broadcast w/q), rg -> row half.

#define IN_DIM   512
#define OUT_DIM  128
#define NEUR     1024
#define B_TOT    512
#define KC       64
#define NMAC     16              // macro steps per chunk (2 kk each)
#define PITCH2   68              // half2 per kk-row (64 entities + 4 pad)
#define NKK      32              // kk rows per chunk
#define ARR2     (NKK*PITCH2)    // 2176 half2 per array
#define BUF2     (3*ARR2)        // x, w, -q
#define SMEM_BYTES (2*BUF2*4)    // 52224 B

typedef unsigned long long u64;

extern __shared__ __half2 smh[];

__device__ __forceinline__ void stage(__half2* base, int kk0, int e,
                                      const float4 px[2], const float4 pw[2], const float4 pq[2])
{
#pragma unroll
    for (int h = 0; h < 2; h++) {
        const int kk = kk0 + h * 16;
        base[(kk    ) * PITCH2 + e]            = __floats2half2_rn(px[h].x, px[h].y);
        base[(kk + 1) * PITCH2 + e]            = __floats2half2_rn(px[h].z, px[h].w);
        base[ARR2 + (kk    ) * PITCH2 + e]     = __floats2half2_rn(pw[h].x, pw[h].y);
        base[ARR2 + (kk + 1) * PITCH2 + e]     = __floats2half2_rn(pw[h].z, pw[h].w);
        base[2*ARR2 + (kk    ) * PITCH2 + e]   = __floats2half2_rn(-pq[h].x, -pq[h].y);
        base[2*ARR2 + (kk + 1) * PITCH2 + e]   = __floats2half2_rn(-pq[h].z, -pq[h].w);
    }
}

__global__ __launch_bounds__(512, 1)
void dnm_kernel(const float* __restrict__ x,
                const float* __restrict__ W,
                const float* __restrict__ q,
                float* __restrict__ out)
{
    const int t    = threadIdx.x;
    const int lane = t & 31;
    const int wid  = t >> 5;
    const int tx   = lane & 15;
    const int ty   = lane >> 4;       // kk parity within macro step
    const int cg   = wid & 7;         // neuron cols cg*8 .. cg*8+7 (one m-group)
    const int rg   = wid >> 3;        // batch rows rg*32 + tx*2 + {0,1}
    const int n0   = blockIdx.x * 64;
    const int b0   = blockIdx.y * 64;

    // global load mapping: 8 threads per entity row, float4 at kq and kq+32
    const int e  = t >> 3;
    const int kq = (t & 7) * 4;
    const float* xg = x + (size_t)(b0 + e) * IN_DIM + kq;
    const float* wg = W + (size_t)(n0 + e) * IN_DIM + kq;
    const float* qg = q + (size_t)(n0 + e) * IN_DIM + kq;
    const int kk0 = kq >> 1;          // 0..14 even

    // f32 totals: rows {0,1} x 8 cols
    float2 facc[2][8];
#pragma unroll
    for (int r = 0; r < 2; r++)
#pragma unroll
        for (int g = 0; g < 8; g++) facc[r][g] = make_float2(0.f, 0.f);

    const __half2 hzero = __float2half2_rn(0.f);

    float4 px[2], pw[2], pq[2];

    // ---- prologue: load + stage chunk 0
#pragma unroll
    for (int h = 0; h < 2; h++) {
        px[h] = *(const float4*)(xg + h * 32);
        pw[h] = *(const float4*)(wg + h * 32);
        pq[h] = *(const float4*)(qg + h * 32);
    }
    stage(smh, kk0, e, px, pw, pq);
    __syncthreads();

    const int NCHUNK = IN_DIM / KC;   // 8

    for (int c = 0; c < NCHUNK; c++) {
        // global prefetch for chunk c+1 (staged mid-loop below)
        if (c < NCHUNK - 1) {
            const int kn = (c + 1) * KC;
#pragma unroll
            for (int h = 0; h < 2; h++) {
                px[h] = *(const float4*)(xg + kn + h * 32);
                pw[h] = *(const float4*)(wg + kn + h * 32);
                pq[h] = *(const float4*)(qg + kn + h * 32);
            }
        }

        const __half2* cb  = smh + (c & 1) * BUF2;
        const __half2* bxp = cb + rg * 32 + tx * 2;
        const __half2* bwp = cb + ARR2 + cg * 8;
        const __half2* bqp = cb + 2 * ARR2 + cg * 8;

        // fp16 chunk accumulators (<= 32 elems per half-lane chain)
        __half2 hacc[2][8];
#pragma unroll
        for (int r = 0; r < 2; r++)
#pragma unroll
            for (int g = 0; g < 8; g++) hacc[r][g] = hzero;

#pragma unroll
        for (int m = 0; m < NMAC; m++) {
            const int off = (2 * m + ty) * PITCH2;

            u64 xv   = *reinterpret_cast<const u64*>(bxp + off);        // rows tx*2, tx*2+1
            uint4 wa = *reinterpret_cast<const uint4*>(bwp + off);      // cols 0-3
            uint4 wb = *reinterpret_cast<const uint4*>(bwp + off + 4);  // cols 4-7
            uint4 qa = *reinterpret_cast<const uint4*>(bqp + off);
            uint4 qb = *reinterpret_cast<const uint4*>(bqp + off + 4);

            // mid-loop: stage prefetched globals into the other smem buffer
            if (m == 8 && c < NCHUNK - 1) {
                stage(smh + ((c + 1) & 1) * BUF2, kk0, e, px, pw, pq);
            }

            const __half2* hx  = reinterpret_cast<const __half2*>(&xv);
            const __half2* hw0 = reinterpret_cast<const __half2*>(&wa);
            const __half2* hw1 = reinterpret_cast<const __half2*>(&wb);
            const __half2* hq0 = reinterpret_cast<const __half2*>(&qa);
            const __half2* hq1 = reinterpret_cast<const __half2*>(&qb);

#pragma unroll
            for (int r = 0; r < 2; r++) {
#pragma unroll
                for (int g = 0; g < 4; g++) {
                    hacc[r][g]     = __hadd2(hacc[r][g],
                                      __hmax2(__hfma2(hx[r], hw0[g], hq0[g]), hzero));
                    hacc[r][g + 4] = __hadd2(hacc[r][g + 4],
                                      __hmax2(__hfma2(hx[r], hw1[g], hq1[g]), hzero));
                }
            }
        }

        // ---- flush fp16 chunk partials into f32 totals
#pragma unroll
        for (int r = 0; r < 2; r++)
#pragma unroll
            for (int g = 0; g < 8; g++) {
                float2 f = __half22float2(hacc[r][g]);
                facc[r][g].x += f.x;
                facc[r][g].y += f.y;
            }

        __syncthreads();
    }

    // ---- epilogue: in-thread sum over 8 cols (one m-group), fold k-parity (xor16)
    const unsigned FULL = 0xffffffffu;
#pragma unroll
    for (int r = 0; r < 2; r++) {
        float s = 0.f;
#pragma unroll
        for (int g = 0; g < 8; g++)
            s += facc[r][g].x + facc[r][g].y;

        s += __shfl_xor_sync(FULL, s, 16);      // fold k parity (ty)

        if (ty == 0) {
            const int b = b0 + rg * 32 + tx * 2 + r;
            const int o = (n0 >> 3) + cg;
            out[b * OUT_DIM + o] = fmaxf(0.25f * s - 0.05f, 0.f);
        }
    }
}

extern "C" void kernel_launch(void* const* d_in, const int* in_sizes, int n_in,
                              void* d_out, int out_size)
{
    const float* x = (const float*)d_in[0];
    const float* W = (const float*)d_in[1];
    const float* q = (const float*)d_in[2];
    float* out = (float*)d_out;

    cudaFuncSetAttribute(dnm_kernel, cudaFuncAttributeMaxDynamicSharedMemorySize, SMEM_BYTES);

    dim3 grid(NEUR / 64, B_TOT / 64);   // 128 CTAs, 512 threads
    dnm_kernel<<<grid, 512, SMEM_BYTES>>>(x, W, q, out);
}